// round 13
// baseline (speedup 1.0000x reference)
#include <cuda_runtime.h>
#include <cstdint>

#define Bz 32
#define Hh 512
#define Ll 2
#define Tt 20
#define Vv 10000
#define Ss 49
#define GRID 148

typedef unsigned long long ull;

// ---------------- device state (no allocations allowed) ----------------
__device__ __align__(16) float g_embT[Hh * Bz];          // k4b4 layout
__device__ __align__(16) float g_hA[Ll][Hh * Bz];        // gated h (LSTM input), k4b4
__device__ __align__(16) float g_hB[Ll][Hh * Bz];        // post-LSTM h, k4b4
__device__ __align__(16) float g_cT[Ll][Hh * Bz];        // plain [k*32+b]
__device__ __align__(16) float g_attnT[Ll][Hh * Bz];     // k4b4
__device__ float g_q[Ll][Hh][Bz];
__device__ float g_keysT[Bz * Ss * Hh];                  // [b][s][d]
__device__ float g_vals[Bz * Ss * Hh];                   // [b][s][d]
__device__ ull   g_amax[Bz];
// two-level monotonic barriers: 8 padded sub-counters + master + gen, never reset
__device__ int g_subF[8 * 32], g_mF, g_genF;
__device__ int g_subA[8 * 32], g_mA, g_genA;
__device__ int g_subB[8 * 32], g_mB, g_genB;

// ---------------- helpers ----------------
__device__ __forceinline__ void fma2(ull& d, ull a, ull b) {
    asm("fma.rn.f32x2 %0, %1, %2, %0;" : "+l"(d) : "l"(a), "l"(b));
}
__device__ __forceinline__ float unpk_sum(ull v) {
    float lo, hi;
    asm("mov.b64 {%0,%1}, %2;" : "=f"(lo), "=f"(hi) : "l"(v));
    return lo + hi;
}
__device__ __forceinline__ longlong2 ldg_cs(const longlong2* p) {
    longlong2 v;
    asm("ld.global.cs.v2.u64 {%0,%1}, [%2];" : "=l"(v.x), "=l"(v.y) : "l"(p));
    return v;
}
__device__ __forceinline__ void stg_cs(float* p, float v) {
    asm("st.global.cs.f32 [%0], %1;" :: "l"(p), "f"(v) : "memory");
}
__device__ __forceinline__ int K4B(int k, int b) { return ((k >> 2) * Bz + b) * 4 + (k & 3); }
__device__ __forceinline__ float sigf(float x) { return 1.0f / (1.0f + expf(-x)); }
__device__ __forceinline__ unsigned fkey(float f) {
    unsigned u = __float_as_uint(f);
    return (u & 0x80000000u) ? ~u : (u | 0x80000000u);
}

// two-level barrier over n blocks; idx = local block index in [0,n); gen is the
// ABSOLUTE generation for this barrier object (monotonic counters, no resets).
__device__ __forceinline__ void bar2(int* sub, int* master, int* genp,
                                     int idx, int n, int gen) {
    __syncthreads();
    if (threadIdx.x == 0) {
        int r = idx & 7;
        int subsize = (n >> 3) + (((n & 7) > r) ? 1 : 0);
        __threadfence();
        bool rel = false;
        if (atomicAdd(&sub[r * 32], 1) == subsize * gen - 1) {
            if (atomicAdd(master, 1) == 8 * gen - 1) {
                asm volatile("st.release.gpu.b32 [%0], %1;" :: "l"(genp), "r"(gen) : "memory");
                rel = true;
            }
        }
        if (!rel) {
            int v;
            do {
                asm volatile("ld.acquire.gpu.b32 %0, [%1];" : "=r"(v) : "l"(genp) : "memory");
            } while (v < gen);
        }
    }
    __syncthreads();
}

// ---------------- keys/values precompute (separate kernel, once per launch) ----------------
__global__ void k_kv(const float* __restrict__ img, const float* __restrict__ Wk,
                     const float* __restrict__ bk, const float* __restrict__ Wv,
                     const float* __restrict__ bv) {
    int bd = blockIdx.x;               // b*512 + d
    int b = bd >> 9, d = bd & 511;
    __shared__ float ch[Ss];
    int tid = threadIdx.x;
    if (tid < Ss) ch[tid] = img[(b * Hh + d) * Ss + tid];
    __syncthreads();
    if (tid < Ss) {
        int s = tid;
        float ka = bk[s], va = bv[s];
        const float* wkr = Wk + s * Ss;
        const float* wvr = Wv + s * Ss;
#pragma unroll
        for (int s2 = 0; s2 < Ss; s2++) {
            float c = ch[s2];
            ka = fmaf(c, wkr[s2], ka);
            va = fmaf(c, wvr[s2], va);
        }
        g_keysT[(b * Ss + s) * Hh + d] = tanhf(ka);
        g_vals[(b * Ss + s) * Hh + d] = tanhf(va);
    }
}

// ================= persistent-kernel phases =================

// copy one 64KB activation array (Hh*Bz floats) into smem
__device__ __forceinline__ void stage1(float4* dst, const float4* src) {
    for (int i = threadIdx.x; i < 4096; i += 512) dst[i] = src[i];
}

// LSTM layer: blocks 0..127, 4 gate-rows per block, split-K=4 (16 warps).
// Activations staged in smem (LDS bypasses L1tex); weights .cs from L2 (1 wf/16B).
__device__ __forceinline__ void phase_lstm(
    float* red, float4* sm0, float4* sm1, const float* xsrc, int layer,
    const longlong2* __restrict__ Wih, const longlong2* __restrict__ Whh,
    const float* __restrict__ bih, const float* __restrict__ bhh) {
    int blk = blockIdx.x;
    if (blk >= 128) return;
    stage1(sm0, (const float4*)xsrc);
    stage1(sm1, (const float4*)g_hA[layer]);
    __syncthreads();
    const longlong2* xT = (const longlong2*)sm0;
    const longlong2* hT = (const longlong2*)sm1;
    int tid = threadIdx.x;
    int wid = tid >> 5, b = tid & 31;
    int rl = wid >> 2, split = wid & 3;
    int jj = blk * 4 + rl;

    ull acc[4] = {0ull, 0ull, 0ull, 0ull};
    int k4b = split * 32;
#pragma unroll 2
    for (int i = 0; i < 32; i++) {
        int k4 = k4b + i;
        longlong2 xv = xT[k4 * Bz + b];
        longlong2 hv = hT[k4 * Bz + b];
#pragma unroll
        for (int g = 0; g < 4; g++) {
            longlong2 wi = ldg_cs(&Wih[(g * Hh + jj) * (Hh / 4) + k4]);
            longlong2 wh = ldg_cs(&Whh[(g * Hh + jj) * (Hh / 4) + k4]);
            fma2(acc[g], (ull)wi.x, (ull)xv.x);
            fma2(acc[g], (ull)wi.y, (ull)xv.y);
            fma2(acc[g], (ull)wh.x, (ull)hv.x);
            fma2(acc[g], (ull)wh.y, (ull)hv.y);
        }
    }
#pragma unroll
    for (int g = 0; g < 4; g++)
        red[((rl * 4 + split) * 4 + g) * 32 + b] = unpk_sum(acc[g]);
    __syncthreads();
    if (tid < 128) {
        int r2 = tid >> 5, bb = tid & 31;
        int j2 = blk * 4 + r2;
        float gate[4];
#pragma unroll
        for (int g = 0; g < 4; g++) {
            float s = 0.f;
#pragma unroll
            for (int sp = 0; sp < 4; sp++) s += red[((r2 * 4 + sp) * 4 + g) * 32 + bb];
            gate[g] = s + bih[g * Hh + j2] + bhh[g * Hh + j2];
        }
        float iv = sigf(gate[0]), fv = sigf(gate[1]);
        float gv = tanhf(gate[2]), ov = sigf(gate[3]);
        int ci = j2 * Bz + bb;
        float c2 = fv * g_cT[layer][ci] + iv * gv;
        g_cT[layer][ci] = c2;
        g_hB[layer][K4B(j2, bb)] = ov * tanhf(c2);
    }
}

// projection over nblk blocks starting at blk0. tasks 0..1249 of 8 vocab rows each.
// Source activations staged in smem; weights .cs streams.
__device__ __forceinline__ void phase_proj(
    ull* samax, float4* sm0, const longlong2* __restrict__ W, const float* __restrict__ pb,
    float* __restrict__ res, int t, int src_emb, int do_amax, int blk0, int nblk) {
    int tid = threadIdx.x;
    if (do_amax && tid < Bz) samax[tid] = 0ull;
    stage1(sm0, src_emb ? (const float4*)g_embT : (const float4*)g_hB[1]);
    __syncthreads();
    int task = (tid >> 5) * nblk + (blockIdx.x - blk0);
    int b = tid & 31;
    const longlong2* xT = (const longlong2*)sm0;
    if (task < 1250) {
        int v0 = task * 8;
        ull acc[8] = {0ull, 0ull, 0ull, 0ull, 0ull, 0ull, 0ull, 0ull};
#pragma unroll 2
        for (int k4 = 0; k4 < Hh / 4; k4++) {
            longlong2 xv = xT[k4 * Bz + b];
#pragma unroll
            for (int r = 0; r < 8; r++) {
                longlong2 wv = ldg_cs(&W[(v0 + r) * (Hh / 4) + k4]);
                fma2(acc[r], (ull)wv.x, (ull)xv.x);
                fma2(acc[r], (ull)wv.y, (ull)xv.y);
            }
        }
        ull best = 0ull;
#pragma unroll
        for (int r = 0; r < 8; r++) {
            int v = v0 + r;
            float lg = unpk_sum(acc[r]) + pb[v];
            stg_cs(&res[b * (Vv * Tt) + v * Tt + t], lg);
            ull pk = ((ull)fkey(lg) << 32) | (unsigned)(~(unsigned)v);
            if (pk > best) best = pk;
        }
        if (do_amax) atomicMax(&samax[b], best);
    }
    if (do_amax) { __syncthreads(); if (tid < Bz) atomicMax(&g_amax[tid], samax[tid]); }
}

// q = tanh(h @ Wq^T + bq). Group B (48 blocks): warp task = one d, both layers, full K.
__device__ __forceinline__ void phase_q(float4* sm0, float4* sm1,
                                        const longlong2* __restrict__ Wq,
                                        const float* __restrict__ bq) {
    stage1(sm0, (const float4*)g_hB[0]);
    stage1(sm1, (const float4*)g_hB[1]);
    __syncthreads();
    int tid = threadIdx.x;
    int d = (tid >> 5) * 48 + blockIdx.x;     // 0..511
    int b = tid & 31;
    if (d < Hh) {
        const longlong2* h0 = (const longlong2*)sm0;
        const longlong2* h1 = (const longlong2*)sm1;
        ull a0 = 0ull, a1 = 0ull;
#pragma unroll 4
        for (int k4 = 0; k4 < Hh / 4; k4++) {
            longlong2 wv = ldg_cs(&Wq[d * (Hh / 4) + k4]);
            longlong2 x0 = h0[k4 * Bz + b];
            longlong2 x1 = h1[k4 * Bz + b];
            fma2(a0, (ull)wv.x, (ull)x0.x);
            fma2(a0, (ull)wv.y, (ull)x0.y);
            fma2(a1, (ull)wv.x, (ull)x1.x);
            fma2(a1, (ull)wv.y, (ull)x1.y);
        }
        float bv = bq[d];
        g_q[0][d][b] = tanhf(unpk_sum(a0) + bv);
        g_q[1][d][b] = tanhf(unpk_sum(a1) + bv);
    }
}

// attention: tasks (l,b) over blocks 0..47 (blocks <16 do two). Coalesced keys/vals.
__device__ __forceinline__ void phase_att(float* sq, float* sw) {
    int tid = threadIdx.x;
    for (int task = blockIdx.x; task < 64; task += 48) {
        int l = task >> 5, b = task & 31;
        __syncthreads();
        for (int d = tid; d < Hh; d += 512) sq[d] = g_q[l][d][b];
        __syncthreads();
        int w = tid >> 5, lane = tid & 31;
        for (int s = w; s < Ss; s += 16) {
            const float* kr = g_keysT + (b * Ss + s) * Hh;
            float acc = 0.f;
            for (int d = lane; d < Hh; d += 32) acc = fmaf(sq[d], kr[d], acc);
#pragma unroll
            for (int o = 16; o > 0; o >>= 1) acc += __shfl_down_sync(0xffffffffu, acc, o);
            if (lane == 0) sw[s] = acc * (1.0f / 7.0f);
        }
        __syncthreads();
        if (w == 0) {
            float v0 = (lane < Ss) ? sw[lane] : -3.4e38f;
            float v1 = (lane + 32 < Ss) ? sw[lane + 32] : -3.4e38f;
            float m = fmaxf(v0, v1);
#pragma unroll
            for (int o = 16; o > 0; o >>= 1) m = fmaxf(m, __shfl_xor_sync(0xffffffffu, m, o));
            float e0 = (lane < Ss) ? expf(v0 - m) : 0.f;
            float e1 = (lane + 32 < Ss) ? expf(v1 - m) : 0.f;
            float sum = e0 + e1;
#pragma unroll
            for (int o = 16; o > 0; o >>= 1) sum += __shfl_xor_sync(0xffffffffu, sum, o);
            float inv = 1.0f / sum;
            if (lane < Ss) sw[lane] = e0 * inv;
            if (lane + 32 < Ss) sw[lane + 32] = e1 * inv;
        }
        __syncthreads();
        for (int d = tid; d < Hh; d += 512) {
            float a = 0.f;
#pragma unroll
            for (int s = 0; s < Ss; s++)
                a = fmaf(sw[s], g_vals[(b * Ss + s) * Hh + d], a);
            g_attnT[l][K4B(d, b)] = a;
        }
    }
}

// greedy-token embedding gather: blocks 48..79 (one per batch element).
__device__ __forceinline__ void phase_gather(const float* __restrict__ embed) {
    int b = blockIdx.x - 48;
    unsigned vtok = ~(unsigned)(g_amax[b]);
    int k = threadIdx.x;
    g_embT[K4B(k, b)] = embed[(size_t)vtok * Hh + k];
    __syncthreads();
    if (threadIdx.x == 0) g_amax[b] = 0ull;
}

// gated hidden update. Blocks 0..31: warp = 8 dims x both layers x split-K=8.
// attnT pair staged in smem; hB read via L1.
__device__ __forceinline__ void phase_hatt(float* red, float4* sm0, float4* sm1,
                                           const longlong2* __restrict__ Wh,
                                           const float* __restrict__ hb) {
    int blk = blockIdx.x;
    if (blk >= 32) return;
    stage1(sm0, (const float4*)g_attnT[0]);
    stage1(sm1, (const float4*)g_attnT[1]);
    __syncthreads();
    int tid = threadIdx.x;
    int wid = tid >> 5, b = tid & 31;
    {
        int dgl = wid >> 3, split = wid & 7;
        int d0 = (blk * 2 + dgl) * 8;
        const longlong2* at0 = (const longlong2*)sm0;
        const longlong2* at1 = (const longlong2*)sm1;
        const longlong2* h0 = (const longlong2*)g_hB[0];
        const longlong2* h1 = (const longlong2*)g_hB[1];
        ull a[8][2] = {};
        int k4b = split * 16;
#pragma unroll 2
        for (int i = 0; i < 16; i++) {
            int k4 = k4b + i;
            longlong2 av0 = at0[k4 * Bz + b], av1 = at1[k4 * Bz + b];
            longlong2 hv0 = h0[k4 * Bz + b], hv1 = h1[k4 * Bz + b];
#pragma unroll
            for (int r = 0; r < 8; r++) {
                longlong2 wA = ldg_cs(&Wh[(d0 + r) * 256 + k4]);
                longlong2 wH = ldg_cs(&Wh[(d0 + r) * 256 + 128 + k4]);
                fma2(a[r][0], (ull)wA.x, (ull)av0.x);
                fma2(a[r][0], (ull)wA.y, (ull)av0.y);
                fma2(a[r][0], (ull)wH.x, (ull)hv0.x);
                fma2(a[r][0], (ull)wH.y, (ull)hv0.y);
                fma2(a[r][1], (ull)wA.x, (ull)av1.x);
                fma2(a[r][1], (ull)wA.y, (ull)av1.y);
                fma2(a[r][1], (ull)wH.x, (ull)hv1.x);
                fma2(a[r][1], (ull)wH.y, (ull)hv1.y);
            }
        }
#pragma unroll
        for (int r = 0; r < 8; r++) {
            red[(wid * 16 + r * 2 + 0) * 32 + b] = unpk_sum(a[r][0]);
            red[(wid * 16 + r * 2 + 1) * 32 + b] = unpk_sum(a[r][1]);
        }
    }
    __syncthreads();
    for (int o = tid; o < 1024; o += 512) {
        int dgl = o >> 9, r = (o >> 6) & 7, l = (o >> 5) & 1, bb = o & 31;
        float s = 0.f;
#pragma unroll
        for (int sp = 0; sp < 8; sp++)
            s += red[((dgl * 8 + sp) * 16 + r * 2 + l) * 32 + bb];
        int d = (blk * 2 + dgl) * 8 + r;
        g_hA[l][K4B(d, bb)] = tanhf(s + hb[d]);
    }
}

// ---------------- the persistent time-loop kernel ----------------
__global__ __launch_bounds__(512, 1) void k_loop(
    const float* __restrict__ pooled, const float* __restrict__ embed,
    const int* __restrict__ sosp,
    const longlong2* __restrict__ Wih, const longlong2* __restrict__ Whh,
    const float* __restrict__ bih, const float* __restrict__ bhh,
    const longlong2* __restrict__ projW, const float* __restrict__ projb,
    const longlong2* __restrict__ Wq, const float* __restrict__ bq,
    const longlong2* __restrict__ hattW, const float* __restrict__ hattb,
    float* __restrict__ res) {
    extern __shared__ float dyn[];       // 128KB: two 64KB activation staging buffers
    float4* sm0 = (float4*)dyn;
    float4* sm1 = (float4*)(dyn + 16384);
    __shared__ float red[8192];          // 32KB reductions
    __shared__ float sq[Hh];
    __shared__ float sw[64];
    __shared__ ull samax[Bz];
    __shared__ int s_bF, s_bA, s_bB;

    if (threadIdx.x == 0) {
        s_bF = *(volatile int*)&g_genF;
        s_bA = *(volatile int*)&g_genA;
        s_bB = *(volatile int*)&g_genB;
    }
    __syncthreads();
    int genF = s_bF, genA = s_bA, genB = s_bB;

    // ---- init ----
    {
        int i = blockIdx.x * 512 + threadIdx.x;
        int sos = sosp[0];
        if (i < Ll * Hh * Bz) {
            int l = i / (Hh * Bz);
            int r = i % (Hh * Bz);
            int k = r >> 5, b = r & 31;
            float pv = pooled[b * Hh + k];
            g_hA[l][K4B(k, b)] = pv;
            g_cT[l][k * Bz + b] = pv;
        }
        if (i < Hh * Bz) {
            int k = i >> 5, b = i & 31;
            g_embT[K4B(k, b)] = embed[sos * Hh + k];
        }
        if (i < Bz) g_amax[i] = 0ull;
    }
    bar2(g_subF, &g_mF, &g_genF, blockIdx.x, GRID, ++genF);

    // t = 0 column from the <SOS> embedding (all blocks, no argmax)
    phase_proj(samax, sm0, projW, projb, res, 0, 1, 0, 0, GRID);
    bar2(g_subF, &g_mF, &g_genF, blockIdx.x, GRID, ++genF);

    const longlong2* Wih1 = Wih + 4 * Hh * (Hh / 4);
    const longlong2* Whh1 = Whh + 4 * Hh * (Hh / 4);

    for (int t = 1; t < Tt; t++) {
        phase_lstm(red, sm0, sm1, g_embT, 0, Wih, Whh, bih, bhh);
        bar2(g_subF, &g_mF, &g_genF, blockIdx.x, GRID, ++genF);
        phase_lstm(red, sm0, sm1, g_hB[0], 1, Wih1, Whh1, bih + 4 * Hh, bhh + 4 * Hh);
        bar2(g_subF, &g_mF, &g_genF, blockIdx.x, GRID, ++genF);
        if (blockIdx.x >= 48) {
            // group A: projection + argmax -> next-token embedding gather
            phase_proj(samax, sm0, projW, projb, res, t, 0, 1, 48, 100);
            bar2(g_subA, &g_mA, &g_genA, blockIdx.x - 48, 100, ++genA);
            if (blockIdx.x < 80) phase_gather(embed);
        } else {
            // group B: q -> attention -> gated hidden update
            phase_q(sm0, sm1, Wq, bq);
            bar2(g_subB, &g_mB, &g_genB, blockIdx.x, 48, ++genB);
            phase_att(sq, sw);
            bar2(g_subB, &g_mB, &g_genB, blockIdx.x, 48, ++genB);
            phase_hatt(red, sm0, sm1, hattW, hattb);
        }
        bar2(g_subF, &g_mF, &g_genF, blockIdx.x, GRID, ++genF);
    }
}

// ---------------- launch ----------------
extern "C" void kernel_launch(void* const* d_in, const int* in_sizes, int n_in,
                              void* d_out, int out_size) {
    (void)in_sizes; (void)n_in; (void)out_size;
    const float* img    = (const float*)d_in[0];
    const float* pooled = (const float*)d_in[1];
    const float* embed  = (const float*)d_in[2];
    const float* Wq     = (const float*)d_in[3];
    const float* bq     = (const float*)d_in[4];
    const float* Wk     = (const float*)d_in[5];
    const float* bk     = (const float*)d_in[6];
    const float* Wv     = (const float*)d_in[7];
    const float* bv     = (const float*)d_in[8];
    const float* Wih    = (const float*)d_in[9];
    const float* Whh    = (const float*)d_in[10];
    const float* bih    = (const float*)d_in[11];
    const float* bhh    = (const float*)d_in[12];
    const float* projW  = (const float*)d_in[13];
    const float* projb  = (const float*)d_in[14];
    const float* hattW  = (const float*)d_in[15];
    const float* hattb  = (const float*)d_in[16];
    const int*   sosp   = (const int*)d_in[17];
    float* res = (float*)d_out;

    cudaFuncSetAttribute(k_loop, cudaFuncAttributeMaxDynamicSharedMemorySize, 131072);
    k_kv<<<Bz * Hh, 64>>>(img, Wk, bk, Wv, bv);
    k_loop<<<GRID, 512, 131072>>>(pooled, embed, sosp,
                                  (const longlong2*)Wih, (const longlong2*)Whh, bih, bhh,
                                  (const longlong2*)projW, projb,
                                  (const longlong2*)Wq, bq,
                                  (const longlong2*)hattW, hattb,
                                  res);
}

// round 14
// speedup vs baseline: 1.0472x; 1.0472x over previous
#include <cuda_runtime.h>
#include <cstdint>

#define Bz 32
#define Hh 512
#define Ll 2
#define Tt 20
#define Vv 10000
#define Ss 49
#define GRID 148

typedef unsigned long long ull;

// ---------------- device state (no allocations allowed) ----------------
__device__ __align__(16) float g_embT[Hh * Bz];          // k4b4 layout
__device__ __align__(16) float g_hA[Ll][Hh * Bz];        // gated h (LSTM input), k4b4
__device__ __align__(16) float g_hB[Ll][Hh * Bz];        // post-LSTM h, k4b4
__device__ __align__(16) float g_cT[Ll][Hh * Bz];        // plain [k*32+b]
__device__ __align__(16) float g_attnT[Ll][Hh * Bz];     // k4b4
__device__ float g_q[Ll][Hh][Bz];
__device__ float g_keysT[Bz * Ss * Hh];                  // [b][s][d]
__device__ float g_vals[Bz * Ss * Hh];                   // [b][s][d]  (coalesced attn reads)
__device__ ull   g_amax[Bz];
// two-level monotonic barriers: 8 padded sub-counters + master + gen, never reset
__device__ int g_subF[8 * 32], g_mF, g_genF;
__device__ int g_subA[8 * 32], g_mA, g_genA;
__device__ int g_subB[8 * 32], g_mB, g_genB;

// ---------------- helpers ----------------
__device__ __forceinline__ void fma2(ull& d, ull a, ull b) {
    asm("fma.rn.f32x2 %0, %1, %2, %0;" : "+l"(d) : "l"(a), "l"(b));
}
__device__ __forceinline__ float unpk_sum(ull v) {
    float lo, hi;
    asm("mov.b64 {%0,%1}, %2;" : "=f"(lo), "=f"(hi) : "l"(v));
    return lo + hi;
}
__device__ __forceinline__ longlong2 ldg_cs(const longlong2* p) {
    longlong2 v;
    asm("ld.global.cs.v2.u64 {%0,%1}, [%2];" : "=l"(v.x), "=l"(v.y) : "l"(p));
    return v;
}
__device__ __forceinline__ void stg_cs(float* p, float v) {
    asm("st.global.cs.f32 [%0], %1;" :: "l"(p), "f"(v) : "memory");
}
__device__ __forceinline__ int K4B(int k, int b) { return ((k >> 2) * Bz + b) * 4 + (k & 3); }
__device__ __forceinline__ float sigf(float x) { return 1.0f / (1.0f + expf(-x)); }
__device__ __forceinline__ unsigned fkey(float f) {
    unsigned u = __float_as_uint(f);
    return (u & 0x80000000u) ? ~u : (u | 0x80000000u);
}

// two-level barrier over n blocks; idx = local block index in [0,n); gen is the
// ABSOLUTE generation for this barrier object (monotonic counters, no resets).
__device__ __forceinline__ void bar2(int* sub, int* master, int* genp,
                                     int idx, int n, int gen) {
    __syncthreads();
    if (threadIdx.x == 0) {
        int r = idx & 7;
        int subsize = (n >> 3) + (((n & 7) > r) ? 1 : 0);
        __threadfence();
        bool rel = false;
        if (atomicAdd(&sub[r * 32], 1) == subsize * gen - 1) {
            if (atomicAdd(master, 1) == 8 * gen - 1) {
                asm volatile("st.release.gpu.b32 [%0], %1;" :: "l"(genp), "r"(gen) : "memory");
                rel = true;
            }
        }
        if (!rel) {
            int v;
            do {
                asm volatile("ld.acquire.gpu.b32 %0, [%1];" : "=r"(v) : "l"(genp) : "memory");
            } while (v < gen);
        }
    }
    __syncthreads();
}

// ---------------- keys/values precompute (separate kernel, once per launch) ----------------
__global__ void k_kv(const float* __restrict__ img, const float* __restrict__ Wk,
                     const float* __restrict__ bk, const float* __restrict__ Wv,
                     const float* __restrict__ bv) {
    int bd = blockIdx.x;               // b*512 + d
    int b = bd >> 9, d = bd & 511;
    __shared__ float ch[Ss];
    int tid = threadIdx.x;
    if (tid < Ss) ch[tid] = img[(b * Hh + d) * Ss + tid];
    __syncthreads();
    if (tid < Ss) {
        int s = tid;
        float ka = bk[s], va = bv[s];
        const float* wkr = Wk + s * Ss;
        const float* wvr = Wv + s * Ss;
#pragma unroll
        for (int s2 = 0; s2 < Ss; s2++) {
            float c = ch[s2];
            ka = fmaf(c, wkr[s2], ka);
            va = fmaf(c, wvr[s2], va);
        }
        g_keysT[(b * Ss + s) * Hh + d] = tanhf(ka);
        g_vals[(b * Ss + s) * Hh + d] = tanhf(va);
    }
}

// ================= persistent-kernel phases =================

// LSTM layer: blocks 0..127, 4 gate-rows per block, split-K=4 (16 warps).
// Weights via plain LDG (L1-resident across steps); activations via L1.
__device__ __forceinline__ void phase_lstm(
    float* red, const longlong2* xT, int layer,
    const longlong2* __restrict__ Wih, const longlong2* __restrict__ Whh,
    const float* __restrict__ bih, const float* __restrict__ bhh) {
    int blk = blockIdx.x;
    if (blk >= 128) return;
    int tid = threadIdx.x;
    int wid = tid >> 5, b = tid & 31;
    int rl = wid >> 2, split = wid & 3;
    int jj = blk * 4 + rl;
    const longlong2* hT = (const longlong2*)g_hA[layer];

    ull acc[4] = {0ull, 0ull, 0ull, 0ull};
    int k4b = split * 32;
#pragma unroll 2
    for (int i = 0; i < 32; i++) {
        int k4 = k4b + i;
        longlong2 xv = xT[k4 * Bz + b];
        longlong2 hv = hT[k4 * Bz + b];
#pragma unroll
        for (int g = 0; g < 4; g++) {
            longlong2 wi = Wih[(g * Hh + jj) * (Hh / 4) + k4];
            longlong2 wh = Whh[(g * Hh + jj) * (Hh / 4) + k4];
            fma2(acc[g], (ull)wi.x, (ull)xv.x);
            fma2(acc[g], (ull)wi.y, (ull)xv.y);
            fma2(acc[g], (ull)wh.x, (ull)hv.x);
            fma2(acc[g], (ull)wh.y, (ull)hv.y);
        }
    }
#pragma unroll
    for (int g = 0; g < 4; g++)
        red[((rl * 4 + split) * 4 + g) * 32 + b] = unpk_sum(acc[g]);
    __syncthreads();
    if (tid < 128) {
        int r2 = tid >> 5, bb = tid & 31;
        int j2 = blk * 4 + r2;
        float gate[4];
#pragma unroll
        for (int g = 0; g < 4; g++) {
            float s = 0.f;
#pragma unroll
            for (int sp = 0; sp < 4; sp++) s += red[((r2 * 4 + sp) * 4 + g) * 32 + bb];
            gate[g] = s + bih[g * Hh + j2] + bhh[g * Hh + j2];
        }
        float iv = sigf(gate[0]), fv = sigf(gate[1]);
        float gv = tanhf(gate[2]), ov = sigf(gate[3]);
        int ci = j2 * Bz + bb;
        float c2 = fv * g_cT[layer][ci] + iv * gv;
        g_cT[layer][ci] = c2;
        g_hB[layer][K4B(j2, bb)] = ov * tanhf(c2);
    }
}

// projection over nblk blocks starting at blk0. tasks 0..1249 of 8 vocab rows each.
// Weights streamed with .cs (no L1 pollution); res written with .cs.
__device__ __forceinline__ void phase_proj(
    ull* samax, const longlong2* __restrict__ W, const float* __restrict__ pb,
    float* __restrict__ res, int t, int src_emb, int do_amax, int blk0, int nblk) {
    int tid = threadIdx.x;
    if (do_amax) {
        if (tid < Bz) samax[tid] = 0ull;
        __syncthreads();
    }
    int task = (tid >> 5) * nblk + (blockIdx.x - blk0);
    int b = tid & 31;
    const longlong2* xT = src_emb ? (const longlong2*)g_embT : (const longlong2*)g_hB[1];
    if (task < 1250) {
        int v0 = task * 8;
        ull acc[8] = {0ull, 0ull, 0ull, 0ull, 0ull, 0ull, 0ull, 0ull};
#pragma unroll 2
        for (int k4 = 0; k4 < Hh / 4; k4++) {
            longlong2 xv = xT[k4 * Bz + b];
#pragma unroll
            for (int r = 0; r < 8; r++) {
                longlong2 wv = ldg_cs(&W[(v0 + r) * (Hh / 4) + k4]);
                fma2(acc[r], (ull)wv.x, (ull)xv.x);
                fma2(acc[r], (ull)wv.y, (ull)xv.y);
            }
        }
        ull best = 0ull;
#pragma unroll
        for (int r = 0; r < 8; r++) {
            int v = v0 + r;
            float lg = unpk_sum(acc[r]) + pb[v];
            stg_cs(&res[b * (Vv * Tt) + v * Tt + t], lg);
            ull pk = ((ull)fkey(lg) << 32) | (unsigned)(~(unsigned)v);
            if (pk > best) best = pk;
        }
        if (do_amax) atomicMax(&samax[b], best);
    }
    if (do_amax) { __syncthreads(); if (tid < Bz) atomicMax(&g_amax[tid], samax[tid]); }
}

// q = tanh(h @ Wq^T + bq). Blocks 0..31: warp = 4 dims x both layers x split-K=4.
__device__ __forceinline__ void phase_q(float* red, const longlong2* __restrict__ Wq,
                                        const float* __restrict__ bq) {
    int tid = threadIdx.x;
    int blk = blockIdx.x;
    int wid = tid >> 5, b = tid & 31;
    int task = blk * 16 + wid;
    if (task < 512) {
        int dgl = wid >> 2, split = wid & 3;
        int d0 = (blk * 4 + dgl) * 4;
        const longlong2* h0 = (const longlong2*)g_hB[0];
        const longlong2* h1 = (const longlong2*)g_hB[1];
        ull a[4][2] = {};
        int k4b = split * 32;
#pragma unroll 2
        for (int i = 0; i < 32; i++) {
            int k4 = k4b + i;
            longlong2 x0 = h0[k4 * Bz + b];
            longlong2 x1 = h1[k4 * Bz + b];
#pragma unroll
            for (int r = 0; r < 4; r++) {
                longlong2 wv = ldg_cs(&Wq[(d0 + r) * (Hh / 4) + k4]);
                fma2(a[r][0], (ull)wv.x, (ull)x0.x);
                fma2(a[r][0], (ull)wv.y, (ull)x0.y);
                fma2(a[r][1], (ull)wv.x, (ull)x1.x);
                fma2(a[r][1], (ull)wv.y, (ull)x1.y);
            }
        }
#pragma unroll
        for (int r = 0; r < 4; r++) {
            red[((wid * 4 + r) * 2 + 0) * 32 + b] = unpk_sum(a[r][0]);
            red[((wid * 4 + r) * 2 + 1) * 32 + b] = unpk_sum(a[r][1]);
        }
    }
    __syncthreads();
    if (blk < 32) {
        for (int o = tid; o < 1024; o += 512) {
            int dgl = o >> 8, r = (o >> 6) & 3, l = (o >> 5) & 1, bb = o & 31;
            float s = 0.f;
#pragma unroll
            for (int sp = 0; sp < 4; sp++)
                s += red[(((dgl * 4 + sp) * 4 + r) * 2 + l) * 32 + bb];
            int d = (blk * 4 + dgl) * 4 + r;
            g_q[l][d][bb] = tanhf(s + bq[d]);
        }
    }
}

// attention: tasks (l,b) over blocks 0..47 (two passes for blk<16). Coalesced vals.
__device__ __forceinline__ void phase_att(float* sq, float* sw) {
    int tid = threadIdx.x;
    for (int task = blockIdx.x; task < 64; task += 48) {
        int l = task >> 5, b = task & 31;
        __syncthreads();
        for (int d = tid; d < Hh; d += 512) sq[d] = g_q[l][d][b];
        __syncthreads();
        int w = tid >> 5, lane = tid & 31;
        for (int s = w; s < Ss; s += 16) {
            const float* kr = g_keysT + (b * Ss + s) * Hh;
            float acc = 0.f;
            for (int d = lane; d < Hh; d += 32) acc = fmaf(sq[d], kr[d], acc);
#pragma unroll
            for (int o = 16; o > 0; o >>= 1) acc += __shfl_down_sync(0xffffffffu, acc, o);
            if (lane == 0) sw[s] = acc * (1.0f / 7.0f);
        }
        __syncthreads();
        if (w == 0) {
            float v0 = (lane < Ss) ? sw[lane] : -3.4e38f;
            float v1 = (lane + 32 < Ss) ? sw[lane + 32] : -3.4e38f;
            float m = fmaxf(v0, v1);
#pragma unroll
            for (int o = 16; o > 0; o >>= 1) m = fmaxf(m, __shfl_xor_sync(0xffffffffu, m, o));
            float e0 = (lane < Ss) ? expf(v0 - m) : 0.f;
            float e1 = (lane + 32 < Ss) ? expf(v1 - m) : 0.f;
            float sum = e0 + e1;
#pragma unroll
            for (int o = 16; o > 0; o >>= 1) sum += __shfl_xor_sync(0xffffffffu, sum, o);
            float inv = 1.0f / sum;
            if (lane < Ss) sw[lane] = e0 * inv;
            if (lane + 32 < Ss) sw[lane + 32] = e1 * inv;
        }
        __syncthreads();
        for (int d = tid; d < Hh; d += 512) {
            float a = 0.f;
#pragma unroll
            for (int s = 0; s < Ss; s++)
                a = fmaf(sw[s], g_vals[(b * Ss + s) * Hh + d], a);
            g_attnT[l][K4B(d, b)] = a;
        }
    }
}

// greedy-token embedding gather: blocks 48..79 (one per batch element).
__device__ __forceinline__ void phase_gather(const float* __restrict__ embed) {
    int b = blockIdx.x - 48;
    unsigned vtok = ~(unsigned)(g_amax[b]);
    int k = threadIdx.x;
    g_embT[K4B(k, b)] = embed[(size_t)vtok * Hh + k];
    __syncthreads();
    if (threadIdx.x == 0) g_amax[b] = 0ull;
}

// gated hidden update. Blocks 0..31: warp = 8 dims x both layers x split-K=8.
__device__ __forceinline__ void phase_hatt(float* red, const longlong2* __restrict__ Wh,
                                           const float* __restrict__ hb) {
    int tid = threadIdx.x;
    int blk = blockIdx.x;
    int wid = tid >> 5, b = tid & 31;
    int task = blk * 16 + wid;
    if (task < 512) {
        int dgl = wid >> 3, split = wid & 7;
        int d0 = (blk * 2 + dgl) * 8;
        const longlong2* at0 = (const longlong2*)g_attnT[0];
        const longlong2* at1 = (const longlong2*)g_attnT[1];
        const longlong2* h0 = (const longlong2*)g_hB[0];
        const longlong2* h1 = (const longlong2*)g_hB[1];
        ull a[8][2] = {};
        int k4b = split * 16;
#pragma unroll 2
        for (int i = 0; i < 16; i++) {
            int k4 = k4b + i;
            longlong2 av0 = at0[k4 * Bz + b], av1 = at1[k4 * Bz + b];
            longlong2 hv0 = h0[k4 * Bz + b], hv1 = h1[k4 * Bz + b];
#pragma unroll
            for (int r = 0; r < 8; r++) {
                longlong2 wA = ldg_cs(&Wh[(d0 + r) * 256 + k4]);
                longlong2 wH = ldg_cs(&Wh[(d0 + r) * 256 + 128 + k4]);
                fma2(a[r][0], (ull)wA.x, (ull)av0.x);
                fma2(a[r][0], (ull)wA.y, (ull)av0.y);
                fma2(a[r][0], (ull)wH.x, (ull)hv0.x);
                fma2(a[r][0], (ull)wH.y, (ull)hv0.y);
                fma2(a[r][1], (ull)wA.x, (ull)av1.x);
                fma2(a[r][1], (ull)wA.y, (ull)av1.y);
                fma2(a[r][1], (ull)wH.x, (ull)hv1.x);
                fma2(a[r][1], (ull)wH.y, (ull)hv1.y);
            }
        }
#pragma unroll
        for (int r = 0; r < 8; r++) {
            red[(wid * 16 + r * 2 + 0) * 32 + b] = unpk_sum(a[r][0]);
            red[(wid * 16 + r * 2 + 1) * 32 + b] = unpk_sum(a[r][1]);
        }
    }
    __syncthreads();
    if (blk < 32) {
        for (int o = tid; o < 1024; o += 512) {
            int dgl = o >> 9, r = (o >> 6) & 7, l = (o >> 5) & 1, bb = o & 31;
            float s = 0.f;
#pragma unroll
            for (int sp = 0; sp < 8; sp++)
                s += red[((dgl * 8 + sp) * 16 + r * 2 + l) * 32 + bb];
            int d = (blk * 2 + dgl) * 8 + r;
            g_hA[l][K4B(d, bb)] = tanhf(s + hb[d]);
        }
    }
}

// ---------------- the persistent time-loop kernel ----------------
__global__ __launch_bounds__(512, 1) void k_loop(
    const float* __restrict__ pooled, const float* __restrict__ embed,
    const int* __restrict__ sosp,
    const longlong2* __restrict__ Wih, const longlong2* __restrict__ Whh,
    const float* __restrict__ bih, const float* __restrict__ bhh,
    const longlong2* __restrict__ projW, const float* __restrict__ projb,
    const longlong2* __restrict__ Wq, const float* __restrict__ bq,
    const longlong2* __restrict__ hattW, const float* __restrict__ hattb,
    float* __restrict__ res) {
    __shared__ float red[8192];        // 32KB (lstm / q / hatt reductions)
    __shared__ float sq[Hh];
    __shared__ float sw[64];
    __shared__ ull samax[Bz];
    __shared__ int s_bF, s_bA, s_bB;

    if (threadIdx.x == 0) {
        s_bF = *(volatile int*)&g_genF;
        s_bA = *(volatile int*)&g_genA;
        s_bB = *(volatile int*)&g_genB;
    }
    __syncthreads();
    int genF = s_bF, genA = s_bA, genB = s_bB;

    // ---- init ----
    {
        int i = blockIdx.x * 512 + threadIdx.x;
        int sos = sosp[0];
        if (i < Ll * Hh * Bz) {
            int l = i / (Hh * Bz);
            int r = i % (Hh * Bz);
            int k = r >> 5, b = r & 31;
            float pv = pooled[b * Hh + k];
            g_hA[l][K4B(k, b)] = pv;
            g_cT[l][k * Bz + b] = pv;
        }
        if (i < Hh * Bz) {
            int k = i >> 5, b = i & 31;
            g_embT[K4B(k, b)] = embed[sos * Hh + k];
        }
        if (i < Bz) g_amax[i] = 0ull;
    }
    bar2(g_subF, &g_mF, &g_genF, blockIdx.x, GRID, ++genF);

    // t = 0 column from the <SOS> embedding (all blocks, no argmax)
    phase_proj(samax, projW, projb, res, 0, 1, 0, 0, GRID);
    bar2(g_subF, &g_mF, &g_genF, blockIdx.x, GRID, ++genF);

    const longlong2* Wih1 = Wih + 4 * Hh * (Hh / 4);
    const longlong2* Whh1 = Whh + 4 * Hh * (Hh / 4);

    for (int t = 1; t < Tt; t++) {
        phase_lstm(red, (const longlong2*)g_embT, 0, Wih, Whh, bih, bhh);
        bar2(g_subF, &g_mF, &g_genF, blockIdx.x, GRID, ++genF);
        phase_lstm(red, (const longlong2*)g_hB[0], 1, Wih1, Whh1, bih + 4 * Hh, bhh + 4 * Hh);
        bar2(g_subF, &g_mF, &g_genF, blockIdx.x, GRID, ++genF);
        if (blockIdx.x >= 48) {
            // group A: projection + argmax -> next-token embedding gather
            phase_proj(samax, projW, projb, res, t, 0, 1, 48, 100);
            bar2(g_subA, &g_mA, &g_genA, blockIdx.x - 48, 100, ++genA);
            if (blockIdx.x < 80) phase_gather(embed);
        } else {
            // group B: q -> attention -> gated hidden update
            phase_q(red, Wq, bq);
            bar2(g_subB, &g_mB, &g_genB, blockIdx.x, 48, ++genB);
            phase_att(sq, sw);
            bar2(g_subB, &g_mB, &g_genB, blockIdx.x, 48, ++genB);
            phase_hatt(red, hattW, hattb);
        }
        bar2(g_subF, &g_mF, &g_genF, blockIdx.x, GRID, ++genF);
    }
}

// ---------------- launch ----------------
extern "C" void kernel_launch(void* const* d_in, const int* in_sizes, int n_in,
                              void* d_out, int out_size) {
    (void)in_sizes; (void)n_in; (void)out_size;
    const float* img    = (const float*)d_in[0];
    const float* pooled = (const float*)d_in[1];
    const float* embed  = (const float*)d_in[2];
    const float* Wq     = (const float*)d_in[3];
    const float* bq     = (const float*)d_in[4];
    const float* Wk     = (const float*)d_in[5];
    const float* bk     = (const float*)d_in[6];
    const float* Wv     = (const float*)d_in[7];
    const float* bv     = (const float*)d_in[8];
    const float* Wih    = (const float*)d_in[9];
    const float* Whh    = (const float*)d_in[10];
    const float* bih    = (const float*)d_in[11];
    const float* bhh    = (const float*)d_in[12];
    const float* projW  = (const float*)d_in[13];
    const float* projb  = (const float*)d_in[14];
    const float* hattW  = (const float*)d_in[15];
    const float* hattb  = (const float*)d_in[16];
    const int*   sosp   = (const int*)d_in[17];
    float* res = (float*)d_out;

    k_kv<<<Bz * Hh, 64>>>(img, Wk, bk, Wv, bv);
    k_loop<<<GRID, 512>>>(pooled, embed, sosp,
                          (const longlong2*)Wih, (const longlong2*)Whh, bih, bhh,
                          (const longlong2*)projW, projb,
                          (const longlong2*)Wq, bq,
                          (const longlong2*)hattW, hattb,
                          res);
}

// round 16
// speedup vs baseline: 1.3140x; 1.2547x over previous
#include <cuda_runtime.h>
#include <cstdint>

#define Bz 32
#define Hh 512
#define Ll 2
#define Tt 20
#define Vv 10000
#define Ss 49
#define GRID 148

typedef unsigned long long ull;

// ---------------- device state (no allocations allowed) ----------------
__device__ __align__(16) float g_embT[Hh * Bz];          // k4b4 layout
__device__ __align__(16) float g_hA[Ll][Hh * Bz];        // gated h (LSTM input), k4b4
__device__ __align__(16) float g_hB[Ll][Hh * Bz];        // post-LSTM h, k4b4
__device__ __align__(16) float g_cT[Ll][Hh * Bz];        // plain [k*32+b]
__device__ __align__(16) float g_attnT[Ll][Hh * Bz];     // k4b4
__device__ float g_q[Ll][Hh][Bz];
__device__ float g_keysT[Bz * Ss * Hh];                  // [b][s][d]
__device__ float g_vals[Bz * Ss * Hh];                   // [b][s][d]  (coalesced attn reads)
__device__ ull   g_amax[Bz];
__device__ int   g_count,  g_gen;    // full-grid barrier
__device__ int   gA_count, gA_gen;   // group A (blocks 48..147, n=100)
__device__ int   gB_count, gB_gen;   // group B (blocks 0..47,  n=48)

// ---------------- helpers ----------------
__device__ __forceinline__ void fma2(ull& d, ull a, ull b) {
    asm("fma.rn.f32x2 %0, %1, %2, %0;" : "+l"(d) : "l"(a), "l"(b));
}
__device__ __forceinline__ float unpk_sum(ull v) {
    float lo, hi;
    asm("mov.b64 {%0,%1}, %2;" : "=f"(lo), "=f"(hi) : "l"(v));
    return lo + hi;
}
__device__ __forceinline__ longlong2 ldg_cs(const longlong2* p) {
    longlong2 v;
    asm("ld.global.cs.v2.u64 {%0,%1}, [%2];" : "=l"(v.x), "=l"(v.y) : "l"(p));
    return v;
}
__device__ __forceinline__ void stg_cs(float* p, float v) {
    asm("st.global.cs.f32 [%0], %1;" :: "l"(p), "f"(v) : "memory");
}
__device__ __forceinline__ int K4B(int k, int b) { return ((k >> 2) * Bz + b) * 4 + (k & 3); }
__device__ __forceinline__ float sigf(float x) { return 1.0f / (1.0f + expf(-x)); }
__device__ __forceinline__ unsigned fkey(float f) {
    unsigned u = __float_as_uint(f);
    return (u & 0x80000000u) ? ~u : (u | 0x80000000u);
}

// barrier over n blocks (monotonic generation; co-residency guaranteed at grid=148)
__device__ __forceinline__ void bar_n(int* cnt, int* genp, int n, int gen) {
    __syncthreads();
    if (threadIdx.x == 0) {
        __threadfence();
        if (atomicAdd(cnt, 1) == n - 1) {
            *cnt = 0;
            __threadfence();
            asm volatile("st.release.gpu.b32 [%0], %1;" :: "l"(genp), "r"(gen) : "memory");
        } else {
            int v;
            do {
                asm volatile("ld.acquire.gpu.b32 %0, [%1];" : "=r"(v) : "l"(genp) : "memory");
            } while (v < gen);
        }
    }
    __syncthreads();
}

// ---------------- keys/values precompute (separate kernel, once per launch) ----------------
__global__ void k_kv(const float* __restrict__ img, const float* __restrict__ Wk,
                     const float* __restrict__ bk, const float* __restrict__ Wv,
                     const float* __restrict__ bv) {
    int bd = blockIdx.x;               // b*512 + d
    int b = bd >> 9, d = bd & 511;
    __shared__ float ch[Ss];
    int tid = threadIdx.x;
    if (tid < Ss) ch[tid] = img[(b * Hh + d) * Ss + tid];
    __syncthreads();
    if (tid < Ss) {
        int s = tid;
        float ka = bk[s], va = bv[s];
        const float* wkr = Wk + s * Ss;
        const float* wvr = Wv + s * Ss;
#pragma unroll
        for (int s2 = 0; s2 < Ss; s2++) {
            float c = ch[s2];
            ka = fmaf(c, wkr[s2], ka);
            va = fmaf(c, wvr[s2], va);
        }
        g_keysT[(b * Ss + s) * Hh + d] = tanhf(ka);
        g_vals[(b * Ss + s) * Hh + d] = tanhf(va);
    }
}

// ================= persistent-kernel phases =================

// LSTM layer: blocks 0..127, 4 gate-rows per block, split-K=4 (16 warps).
// Weights staged through a 2KB/warp smem ring: coalesced LDG.128 stages replace
// uniform per-iter LDGs; inner loop reads broadcast LDS.
__device__ __forceinline__ void phase_lstm(
    float* red, longlong2* stg, const longlong2* xT, int layer,
    const longlong2* __restrict__ Wih, const longlong2* __restrict__ Whh,
    const float* __restrict__ bih, const float* __restrict__ bhh) {
    int blk = blockIdx.x;
    if (blk >= 128) return;
    int tid = threadIdx.x;
    int wid = tid >> 5, lane = tid & 31, b = lane;
    int rl = wid >> 2, split = wid & 3;
    int jj = blk * 4 + rl;
    const longlong2* hT = (const longlong2*)g_hA[layer];
    longlong2* ws = stg + wid * 128;   // 2KB per warp

    ull acc[4] = {0ull, 0ull, 0ull, 0ull};
#pragma unroll
    for (int c = 0; c < 2; c++) {
        int base = split * 32 + c * 16;
        // stage 8 rows (Wih g0..3 then Whh g0..3) x 16 ll2 each
        int rr = lane >> 4;
        int li = lane & 15;
#pragma unroll
        for (int j = 0; j < 4; j++) {
            int r = j * 2 + rr;                 // 0..7; r<4 -> Wih, else Whh
            const longlong2* M = (r < 4) ? Wih : Whh;
            ws[r * 16 + li] = M[((r & 3) * Hh + jj) * (Hh / 4) + base + li];
        }
        __syncwarp();
#pragma unroll 2
        for (int i = 0; i < 16; i++) {
            int k4 = base + i;
            longlong2 xv = xT[k4 * Bz + b];
            longlong2 hv = hT[k4 * Bz + b];
#pragma unroll
            for (int g = 0; g < 4; g++) {
                longlong2 wi = ws[g * 16 + i];
                longlong2 wh = ws[(4 + g) * 16 + i];
                fma2(acc[g], (ull)wi.x, (ull)xv.x);
                fma2(acc[g], (ull)wi.y, (ull)xv.y);
                fma2(acc[g], (ull)wh.x, (ull)hv.x);
                fma2(acc[g], (ull)wh.y, (ull)hv.y);
            }
        }
        __syncwarp();
    }
#pragma unroll
    for (int g = 0; g < 4; g++)
        red[((rl * 4 + split) * 4 + g) * 32 + b] = unpk_sum(acc[g]);
    __syncthreads();
    if (tid < 128) {
        int r2 = tid >> 5, bb = tid & 31;
        int j2 = blk * 4 + r2;
        float gate[4];
#pragma unroll
        for (int g = 0; g < 4; g++) {
            float s = 0.f;
#pragma unroll
            for (int sp = 0; sp < 4; sp++) s += red[((r2 * 4 + sp) * 4 + g) * 32 + bb];
            gate[g] = s + bih[g * Hh + j2] + bhh[g * Hh + j2];
        }
        float iv = sigf(gate[0]), fv = sigf(gate[1]);
        float gv = tanhf(gate[2]), ov = sigf(gate[3]);
        int ci = j2 * Bz + bb;
        float c2 = fv * g_cT[layer][ci] + iv * gv;
        g_cT[layer][ci] = c2;
        g_hB[layer][K4B(j2, bb)] = ov * tanhf(c2);
    }
}

// projection over nblk blocks starting at blk0. tasks 0..1249 of 8 vocab rows each.
// Weight chunks staged (coalesced .cs LDG -> broadcast LDS); res written .cs.
__device__ __forceinline__ void phase_proj(
    ull* samax, longlong2* stg, const longlong2* __restrict__ W, const float* __restrict__ pb,
    float* __restrict__ res, int t, int src_emb, int do_amax, int blk0, int nblk) {
    int tid = threadIdx.x;
    if (do_amax) {
        if (tid < Bz) samax[tid] = 0ull;
        __syncthreads();
    }
    int wid = tid >> 5, lane = tid & 31, b = lane;
    int task = wid * nblk + (blockIdx.x - blk0);
    const longlong2* xT = src_emb ? (const longlong2*)g_embT : (const longlong2*)g_hB[1];
    longlong2* ws = stg + wid * 128;   // 2KB per warp
    if (task < 1250) {
        int v0 = task * 8;
        ull acc[8] = {0ull, 0ull, 0ull, 0ull, 0ull, 0ull, 0ull, 0ull};
        int rr = lane >> 4;
        int li = lane & 15;
#pragma unroll 1
        for (int c = 0; c < 8; c++) {
            // stage 8 rows x 16 ll2 (256B per row chunk)
#pragma unroll
            for (int j = 0; j < 4; j++) {
                int r = j * 2 + rr;
                ws[r * 16 + li] = ldg_cs(&W[(v0 + r) * (Hh / 4) + c * 16 + li]);
            }
            __syncwarp();
#pragma unroll 2
            for (int i = 0; i < 16; i++) {
                int k4 = c * 16 + i;
                longlong2 xv = xT[k4 * Bz + b];
#pragma unroll
                for (int r = 0; r < 8; r++) {
                    longlong2 wv = ws[r * 16 + i];
                    fma2(acc[r], (ull)wv.x, (ull)xv.x);
                    fma2(acc[r], (ull)wv.y, (ull)xv.y);
                }
            }
            __syncwarp();
        }
        ull best = 0ull;
#pragma unroll
        for (int r = 0; r < 8; r++) {
            int v = v0 + r;
            float lg = unpk_sum(acc[r]) + pb[v];
            stg_cs(&res[b * (Vv * Tt) + v * Tt + t], lg);
            ull pk = ((ull)fkey(lg) << 32) | (unsigned)(~(unsigned)v);
            if (pk > best) best = pk;
        }
        if (do_amax) atomicMax(&samax[b], best);
    }
    if (do_amax) { __syncthreads(); if (tid < Bz) atomicMax(&g_amax[tid], samax[tid]); }
}

// q = tanh(h @ Wq^T + bq). Blocks 0..31: warp = 4 dims x both layers x split-K=4.
__device__ __forceinline__ void phase_q(float* red, const longlong2* __restrict__ Wq,
                                        const float* __restrict__ bq) {
    int tid = threadIdx.x;
    int blk = blockIdx.x;
    int wid = tid >> 5, b = tid & 31;
    int task = blk * 16 + wid;
    if (task < 512) {
        int dgl = wid >> 2, split = wid & 3;
        int d0 = (blk * 4 + dgl) * 4;
        const longlong2* h0 = (const longlong2*)g_hB[0];
        const longlong2* h1 = (const longlong2*)g_hB[1];
        ull a[4][2] = {};
        int k4b = split * 32;
#pragma unroll 2
        for (int i = 0; i < 32; i++) {
            int k4 = k4b + i;
            longlong2 x0 = h0[k4 * Bz + b];
            longlong2 x1 = h1[k4 * Bz + b];
#pragma unroll
            for (int r = 0; r < 4; r++) {
                longlong2 wv = ldg_cs(&Wq[(d0 + r) * (Hh / 4) + k4]);
                fma2(a[r][0], (ull)wv.x, (ull)x0.x);
                fma2(a[r][0], (ull)wv.y, (ull)x0.y);
                fma2(a[r][1], (ull)wv.x, (ull)x1.x);
                fma2(a[r][1], (ull)wv.y, (ull)x1.y);
            }
        }
#pragma unroll
        for (int r = 0; r < 4; r++) {
            red[((wid * 4 + r) * 2 + 0) * 32 + b] = unpk_sum(a[r][0]);
            red[((wid * 4 + r) * 2 + 1) * 32 + b] = unpk_sum(a[r][1]);
        }
    }
    __syncthreads();
    if (blk < 32) {
        for (int o = tid; o < 1024; o += 512) {
            int dgl = o >> 8, r = (o >> 6) & 3, l = (o >> 5) & 1, bb = o & 31;
            float s = 0.f;
#pragma unroll
            for (int sp = 0; sp < 4; sp++)
                s += red[(((dgl * 4 + sp) * 4 + r) * 2 + l) * 32 + bb];
            int d = (blk * 4 + dgl) * 4 + r;
            g_q[l][d][bb] = tanhf(s + bq[d]);
        }
    }
}

// attention: tasks (l,b) over blocks 0..47 (two passes for blk<16). Coalesced vals.
__device__ __forceinline__ void phase_att(float* sq, float* sw) {
    int tid = threadIdx.x;
    for (int task = blockIdx.x; task < 64; task += 48) {
        int l = task >> 5, b = task & 31;
        __syncthreads();
        for (int d = tid; d < Hh; d += 512) sq[d] = g_q[l][d][b];
        __syncthreads();
        int w = tid >> 5, lane = tid & 31;
        for (int s = w; s < Ss; s += 16) {
            const float* kr = g_keysT + (b * Ss + s) * Hh;
            float acc = 0.f;
            for (int d = lane; d < Hh; d += 32) acc = fmaf(sq[d], kr[d], acc);
#pragma unroll
            for (int o = 16; o > 0; o >>= 1) acc += __shfl_down_sync(0xffffffffu, acc, o);
            if (lane == 0) sw[s] = acc * (1.0f / 7.0f);
        }
        __syncthreads();
        if (w == 0) {
            float v0 = (lane < Ss) ? sw[lane] : -3.4e38f;
            float v1 = (lane + 32 < Ss) ? sw[lane + 32] : -3.4e38f;
            float m = fmaxf(v0, v1);
#pragma unroll
            for (int o = 16; o > 0; o >>= 1) m = fmaxf(m, __shfl_xor_sync(0xffffffffu, m, o));
            float e0 = (lane < Ss) ? expf(v0 - m) : 0.f;
            float e1 = (lane + 32 < Ss) ? expf(v1 - m) : 0.f;
            float sum = e0 + e1;
#pragma unroll
            for (int o = 16; o > 0; o >>= 1) sum += __shfl_xor_sync(0xffffffffu, sum, o);
            float inv = 1.0f / sum;
            if (lane < Ss) sw[lane] = e0 * inv;
            if (lane + 32 < Ss) sw[lane + 32] = e1 * inv;
        }
        __syncthreads();
        for (int d = tid; d < Hh; d += 512) {
            float a = 0.f;
#pragma unroll
            for (int s = 0; s < Ss; s++)
                a = fmaf(sw[s], g_vals[(b * Ss + s) * Hh + d], a);
            g_attnT[l][K4B(d, b)] = a;
        }
    }
}

// greedy-token embedding gather: blocks 48..79 (one per batch element).
__device__ __forceinline__ void phase_gather(const float* __restrict__ embed) {
    int b = blockIdx.x - 48;
    unsigned vtok = ~(unsigned)(g_amax[b]);
    int k = threadIdx.x;
    g_embT[K4B(k, b)] = embed[(size_t)vtok * Hh + k];
    __syncthreads();
    if (threadIdx.x == 0) g_amax[b] = 0ull;
}

// gated hidden update. Blocks 0..31: warp = 8 dims x both layers x split-K=8.
__device__ __forceinline__ void phase_hatt(float* red, const longlong2* __restrict__ Wh,
                                           const float* __restrict__ hb) {
    int tid = threadIdx.x;
    int blk = blockIdx.x;
    int wid = tid >> 5, b = tid & 31;
    int task = blk * 16 + wid;
    if (task < 512) {
        int dgl = wid >> 3, split = wid & 7;
        int d0 = (blk * 2 + dgl) * 8;
        const longlong2* at0 = (const longlong2*)g_attnT[0];
        const longlong2* at1 = (const longlong2*)g_attnT[1];
        const longlong2* h0 = (const longlong2*)g_hB[0];
        const longlong2* h1 = (const longlong2*)g_hB[1];
        ull a[8][2] = {};
        int k4b = split * 16;
#pragma unroll 2
        for (int i = 0; i < 16; i++) {
            int k4 = k4b + i;
            longlong2 av0 = at0[k4 * Bz + b], av1 = at1[k4 * Bz + b];
            longlong2 hv0 = h0[k4 * Bz + b], hv1 = h1[k4 * Bz + b];
#pragma unroll
            for (int r = 0; r < 8; r++) {
                longlong2 wA = ldg_cs(&Wh[(d0 + r) * 256 + k4]);
                longlong2 wH = ldg_cs(&Wh[(d0 + r) * 256 + 128 + k4]);
                fma2(a[r][0], (ull)wA.x, (ull)av0.x);
                fma2(a[r][0], (ull)wA.y, (ull)av0.y);
                fma2(a[r][0], (ull)wH.x, (ull)hv0.x);
                fma2(a[r][0], (ull)wH.y, (ull)hv0.y);
                fma2(a[r][1], (ull)wA.x, (ull)av1.x);
                fma2(a[r][1], (ull)wA.y, (ull)av1.y);
                fma2(a[r][1], (ull)wH.x, (ull)hv1.x);
                fma2(a[r][1], (ull)wH.y, (ull)hv1.y);
            }
        }
#pragma unroll
        for (int r = 0; r < 8; r++) {
            red[(wid * 16 + r * 2 + 0) * 32 + b] = unpk_sum(a[r][0]);
            red[(wid * 16 + r * 2 + 1) * 32 + b] = unpk_sum(a[r][1]);
        }
    }
    __syncthreads();
    if (blk < 32) {
        for (int o = tid; o < 1024; o += 512) {
            int dgl = o >> 9, r = (o >> 6) & 7, l = (o >> 5) & 1, bb = o & 31;
            float s = 0.f;
#pragma unroll
            for (int sp = 0; sp < 8; sp++)
                s += red[((dgl * 8 + sp) * 16 + r * 2 + l) * 32 + bb];
            int d = (blk * 2 + dgl) * 8 + r;
            g_hA[l][K4B(d, bb)] = tanhf(s + hb[d]);
        }
    }
}

// ---------------- the persistent time-loop kernel ----------------
__global__ __launch_bounds__(512, 1) void k_loop(
    const float* __restrict__ pooled, const float* __restrict__ embed,
    const int* __restrict__ sosp,
    const longlong2* __restrict__ Wih, const longlong2* __restrict__ Whh,
    const float* __restrict__ bih, const float* __restrict__ bhh,
    const longlong2* __restrict__ projW, const float* __restrict__ projb,
    const longlong2* __restrict__ Wq, const float* __restrict__ bq,
    const longlong2* __restrict__ hattW, const float* __restrict__ hattb,
    float* __restrict__ res) {
    extern __shared__ longlong2 stg[]; // 32KB dynamic: 2KB/warp weight staging
    __shared__ float red[8192];        // 32KB (lstm / q / hatt reductions)
    __shared__ float sq[Hh];
    __shared__ float sw[64];
    __shared__ ull samax[Bz];
    __shared__ int s_bF, s_bA, s_bB;

    if (threadIdx.x == 0) {
        s_bF = *(volatile int*)&g_gen;
        s_bA = *(volatile int*)&gA_gen;
        s_bB = *(volatile int*)&gB_gen;
    }
    __syncthreads();
    int genF = s_bF, genA = s_bA, genB = s_bB;

    // ---- init ----
    {
        int i = blockIdx.x * 512 + threadIdx.x;
        int sos = sosp[0];
        if (i < Ll * Hh * Bz) {
            int l = i / (Hh * Bz);
            int r = i % (Hh * Bz);
            int k = r >> 5, b = r & 31;
            float pv = pooled[b * Hh + k];
            g_hA[l][K4B(k, b)] = pv;
            g_cT[l][k * Bz + b] = pv;
        }
        if (i < Hh * Bz) {
            int k = i >> 5, b = i & 31;
            g_embT[K4B(k, b)] = embed[sos * Hh + k];
        }
        if (i < Bz) g_amax[i] = 0ull;
    }
    bar_n(&g_count, &g_gen, GRID, ++genF);

    // t = 0 column from the <SOS> embedding (all blocks, no argmax)
    phase_proj(samax, stg, projW, projb, res, 0, 1, 0, 0, GRID);
    bar_n(&g_count, &g_gen, GRID, ++genF);

    const longlong2* Wih1 = Wih + 4 * Hh * (Hh / 4);
    const longlong2* Whh1 = Whh + 4 * Hh * (Hh / 4);

    for (int t = 1; t < Tt; t++) {
        phase_lstm(red, stg, (const longlong2*)g_embT, 0, Wih, Whh, bih, bhh);
        bar_n(&g_count, &g_gen, GRID, ++genF);
        phase_lstm(red, stg, (const longlong2*)g_hB[0], 1, Wih1, Whh1,
                   bih + 4 * Hh, bhh + 4 * Hh);
        bar_n(&g_count, &g_gen, GRID, ++genF);
        if (blockIdx.x >= 48) {
            // group A: projection + argmax -> next-token embedding gather
            phase_proj(samax, stg, projW, projb, res, t, 0, 1, 48, 100);
            bar_n(&gA_count, &gA_gen, 100, ++genA);
            if (blockIdx.x < 80) phase_gather(embed);
        } else {
            // group B: q -> attention -> gated hidden update
            phase_q(red, Wq, bq);
            bar_n(&gB_count, &gB_gen, 48, ++genB);
            phase_att(sq, sw);
            bar_n(&gB_count, &gB_gen, 48, ++genB);
            phase_hatt(red, hattW, hattb);
        }
        bar_n(&g_count, &g_gen, GRID, ++genF);
    }
}

// ---------------- launch ----------------
extern "C" void kernel_launch(void* const* d_in, const int* in_sizes, int n_in,
                              void* d_out, int out_size) {
    (void)in_sizes; (void)n_in; (void)out_size;
    const float* img    = (const float*)d_in[0];
    const float* pooled = (const float*)d_in[1];
    const float* embed  = (const float*)d_in[2];
    const float* Wq     = (const float*)d_in[3];
    const float* bq     = (const float*)d_in[4];
    const float* Wk     = (const float*)d_in[5];
    const float* bk     = (const float*)d_in[6];
    const float* Wv     = (const float*)d_in[7];
    const float* bv     = (const float*)d_in[8];
    const float* Wih    = (const float*)d_in[9];
    const float* Whh    = (const float*)d_in[10];
    const float* bih    = (const float*)d_in[11];
    const float* bhh    = (const float*)d_in[12];
    const float* projW  = (const float*)d_in[13];
    const float* projb  = (const float*)d_in[14];
    const float* hattW  = (const float*)d_in[15];
    const float* hattb  = (const float*)d_in[16];
    const int*   sosp   = (const int*)d_in[17];
    float* res = (float*)d_out;

    // opt-in: static (~34.6KB) + dynamic (32KB) exceeds the default 48KB cap
    cudaFuncSetAttribute(k_loop, cudaFuncAttributeMaxDynamicSharedMemorySize, 65536);
    k_kv<<<Bz * Hh, 64>>>(img, Wk, bk, Wv, bv);
    k_loop<<<GRID, 512, 32768>>>(pooled, embed, sosp,
                                 (const longlong2*)Wih, (const longlong2*)Whh, bih, bhh,
                                 (const longlong2*)projW, projb,
                                 (const longlong2*)Wq, bq,
                                 (const longlong2*)hattW, hattb,
                                 res);
}